// round 1
// baseline (speedup 1.0000x reference)
#include <cuda_runtime.h>
#include <cuda_bf16.h>
#include <math.h>

#define N_NODES 50000
#define N_EDGES 800000
#define F 128
#define EPSW 1e-12f

// ---------------- scratch (device globals; no allocation allowed) ----------
__device__ float g_wdeg_out[N_NODES];
__device__ float g_wdeg_in [N_NODES];
__device__ float g_cnt_out [N_NODES];
__device__ float g_cnt_in  [N_NODES];
__device__ float g_coef    [N_EDGES];
__device__ float g_agg     [(size_t)N_NODES * F];
__device__ float g_h       [(size_t)N_NODES * F];

// ---------------- helpers ---------------------------------------------------
__device__ __forceinline__ float selu_f(float v) {
    const float scale = 1.0507009873554805f;
    const float alpha = 1.6732632423543772f;
    return v > 0.0f ? scale * v : scale * alpha * expm1f(v);
}

// ---------------- kernels ---------------------------------------------------
__global__ void zero_deg_kernel() {
    int i = blockIdx.x * blockDim.x + threadIdx.x;
    if (i < N_NODES) {
        g_wdeg_out[i] = 0.0f;
        g_wdeg_in [i] = 0.0f;
        g_cnt_out [i] = 0.0f;
        g_cnt_in  [i] = 0.0f;
    }
}

__global__ void zero_agg_kernel() {
    int i = blockIdx.x * blockDim.x + threadIdx.x;
    if (i < (N_NODES * F) / 4) {
        ((float4*)g_agg)[i] = make_float4(0.f, 0.f, 0.f, 0.f);
    }
}

__global__ void deg_kernel(const int* __restrict__ src,
                           const int* __restrict__ dst,
                           const float* __restrict__ w) {
    int e = blockIdx.x * blockDim.x + threadIdx.x;
    if (e >= N_EDGES) return;
    float we = w[e];
    int s = src[e], d = dst[e];
    atomicAdd(&g_wdeg_out[s], we);
    atomicAdd(&g_wdeg_in [d], we);
    atomicAdd(&g_cnt_out [s], 1.0f);
    atomicAdd(&g_cnt_in  [d], 1.0f);
}

__global__ void coef_kernel(const int* __restrict__ src,
                            const int* __restrict__ dst,
                            const float* __restrict__ w) {
    int e = blockIdx.x * blockDim.x + threadIdx.x;
    if (e >= N_EDGES) return;
    int s = src[e], d = dst[e];
    float c = w[e]
            * rsqrtf(fmaxf(g_wdeg_out[s], EPSW))
            * rsqrtf(fmaxf(g_wdeg_in [d], EPSW))
            * rsqrtf(fmaxf(g_cnt_out [s], 1.0f))
            * rsqrtf(fmaxf(g_cnt_in  [d], 1.0f));
    g_coef[e] = c;
}

// One warp per edge; each lane handles 4 contiguous features (float4 gather +
// 4 scalar atomic adds into the destination row).
__global__ void spmm_kernel(const float* __restrict__ x,
                            const int* __restrict__ src,
                            const int* __restrict__ dst,
                            int layer) {
    int t = blockIdx.x * blockDim.x + threadIdx.x;
    int e = t >> 5;
    int lane = t & 31;
    if (e >= N_EDGES) return;

    const float* feat = (layer == 0) ? x : g_h;
    float c = g_coef[e];
    int s = src[e];
    int d = dst[e];

    float4 v = *((const float4*)(feat + (size_t)s * F) + lane);
    float* ap = g_agg + (size_t)d * F + lane * 4;
    atomicAdd(ap + 0, c * v.x);
    atomicAdd(ap + 1, c * v.y);
    atomicAdd(ap + 2, c * v.z);
    atomicAdd(ap + 3, c * v.w);
}

// C = selu(g_agg @ W + b).  M = N_NODES, N = K = 128.
// Block: 256 threads, 128x128 tile, 8x8 micro-tile per thread, BK = 8.
__global__ void gemm_bias_selu_kernel(const float* __restrict__ W,
                                      const float* __restrict__ b,
                                      float* __restrict__ outp,
                                      int layer) {
    __shared__ float As[8][128];   // transposed A tile: As[k][m]
    __shared__ float Bs[8][128];   // Bs[k][n]

    const float* A = g_agg;
    float* out = (layer == 0) ? g_h : outp;

    int tid = threadIdx.x;
    int bm = blockIdx.x * 128;
    int ty = tid >> 4;        // 0..15 -> m group
    int tx = tid & 15;        // 0..15 -> n group

    float acc[8][8];
#pragma unroll
    for (int i = 0; i < 8; i++)
#pragma unroll
        for (int j = 0; j < 8; j++) acc[i][j] = 0.0f;

    // A-load mapping: m = tid/2, kq = (tid&1)*4  (one float4 per thread)
    int am = tid >> 1;
    int akq = (tid & 1) * 4;
    int arow = bm + am;
    // B-load mapping: kb = tid/32, nb = (tid&31)*4
    int bkb = tid >> 5;
    int bnb = (tid & 31) * 4;

    for (int k0 = 0; k0 < 128; k0 += 8) {
        float4 av = make_float4(0.f, 0.f, 0.f, 0.f);
        if (arow < N_NODES)
            av = *(const float4*)(A + (size_t)arow * F + k0 + akq);
        As[akq + 0][am] = av.x;
        As[akq + 1][am] = av.y;
        As[akq + 2][am] = av.z;
        As[akq + 3][am] = av.w;

        *(float4*)&Bs[bkb][bnb] = *(const float4*)(W + (size_t)(k0 + bkb) * F + bnb);

        __syncthreads();

#pragma unroll
        for (int k = 0; k < 8; k++) {
            float a[8], bb[8];
#pragma unroll
            for (int i = 0; i < 8; i++) a[i] = As[k][ty * 8 + i];
#pragma unroll
            for (int j = 0; j < 8; j++) bb[j] = Bs[k][tx * 8 + j];
#pragma unroll
            for (int i = 0; i < 8; i++)
#pragma unroll
                for (int j = 0; j < 8; j++)
                    acc[i][j] = fmaf(a[i], bb[j], acc[i][j]);
        }
        __syncthreads();
    }

#pragma unroll
    for (int i = 0; i < 8; i++) {
        int row = bm + ty * 8 + i;
        if (row >= N_NODES) continue;
#pragma unroll
        for (int j = 0; j < 8; j++) {
            int col = tx * 8 + j;
            float v = acc[i][j] + b[col];
            out[(size_t)row * F + col] = selu_f(v);
        }
    }
}

// ---------------- launch ----------------------------------------------------
extern "C" void kernel_launch(void* const* d_in, const int* in_sizes, int n_in,
                              void* d_out, int out_size) {
    const float* x   = (const float*)d_in[0];
    const int*   src = (const int*)  d_in[1];
    const int*   dst = (const int*)  d_in[2];
    const float* ew  = (const float*)d_in[3];
    const float* W1  = (const float*)d_in[4];
    const float* b1  = (const float*)d_in[5];
    const float* W2  = (const float*)d_in[6];
    const float* b2  = (const float*)d_in[7];
    float* out = (float*)d_out;

    const int TB = 256;
    dim3 nodeGrid((N_NODES + TB - 1) / TB);
    dim3 edgeGrid((N_EDGES + TB - 1) / TB);
    dim3 aggGrid((N_NODES * F / 4 + TB - 1) / TB);
    dim3 spmmGrid(((size_t)N_EDGES * 32 + TB - 1) / TB);
    dim3 gemmGrid((N_NODES + 127) / 128);

    // degrees + shared edge coefficient
    zero_deg_kernel<<<nodeGrid, TB>>>();
    deg_kernel<<<edgeGrid, TB>>>(src, dst, ew);
    coef_kernel<<<edgeGrid, TB>>>(src, dst, ew);

    // layer 1: agg = SpMM(coef, x); h = selu(agg @ W1 + b1)
    zero_agg_kernel<<<aggGrid, TB>>>();
    spmm_kernel<<<spmmGrid, TB>>>(x, src, dst, 0);
    gemm_bias_selu_kernel<<<gemmGrid, TB>>>(W1, b1, out, 0);

    // layer 2: agg = SpMM(coef, selu(h)); out = selu(agg @ W2 + b2)
    zero_agg_kernel<<<aggGrid, TB>>>();
    spmm_kernel<<<spmmGrid, TB>>>(x, src, dst, 1);
    gemm_bias_selu_kernel<<<gemmGrid, TB>>>(W2, b2, out, 1);
}

// round 3
// speedup vs baseline: 1.7805x; 1.7805x over previous
#include <cuda_runtime.h>
#include <cuda_bf16.h>
#include <math.h>

#define N_NODES 50000
#define N_EDGES 800000
#define F 128
#define EPSW 1e-12f

// ---------------- scratch (device globals; no allocation allowed) ----------
__device__ float g_wdeg_out[N_NODES];
__device__ float g_wdeg_in [N_NODES];
__device__ int   g_cnt_out [N_NODES];
__device__ int   g_hist_in [N_NODES];   // dst histogram (also cnt_in)
__device__ int   g_row_start[N_NODES + 1];
__device__ int   g_cursor  [N_NODES];
__device__ int   g_csr_src [N_EDGES];
__device__ float g_csr_coef[N_EDGES];
__device__ float g_agg     [(size_t)N_NODES * F];
__device__ float g_h       [(size_t)N_NODES * F];

// ---------------- helpers ---------------------------------------------------
__device__ __forceinline__ float selu_f(float v) {
    const float scale = 1.0507009873554805f;
    const float alpha = 1.6732632423543772f;
    return v > 0.0f ? scale * v : scale * alpha * expm1f(v);
}

// ---------------- kernels ---------------------------------------------------
__global__ void zero_deg_kernel() {
    int i = blockIdx.x * blockDim.x + threadIdx.x;
    if (i < N_NODES) {
        g_wdeg_out[i] = 0.0f;
        g_wdeg_in [i] = 0.0f;
        g_cnt_out [i] = 0;
        g_hist_in [i] = 0;
    }
}

__global__ void deg_kernel(const int* __restrict__ src,
                           const int* __restrict__ dst,
                           const float* __restrict__ w) {
    int e = blockIdx.x * blockDim.x + threadIdx.x;
    if (e >= N_EDGES) return;
    float we = w[e];
    int s = src[e], d = dst[e];
    atomicAdd(&g_wdeg_out[s], we);
    atomicAdd(&g_wdeg_in [d], we);
    atomicAdd(&g_cnt_out [s], 1);
    atomicAdd(&g_hist_in [d], 1);
}

// Single-block exclusive scan of g_hist_in -> g_row_start / g_cursor.
__global__ void scan_kernel() {
    const int T = 1024;
    __shared__ int warp_sums[32];
    int t = threadIdx.x;
    const int chunk = (N_NODES + T - 1) / T;   // 49
    int begin = t * chunk;
    int end = min(begin + chunk, N_NODES);

    int local = 0;
    for (int i = begin; i < end; i++) local += g_hist_in[i];

    // block exclusive scan of thread-local sums
    int lane = t & 31, wid = t >> 5;
    int v = local;
    #pragma unroll
    for (int off = 1; off < 32; off <<= 1) {
        int n = __shfl_up_sync(0xffffffff, v, off);
        if (lane >= off) v += n;
    }
    if (lane == 31) warp_sums[wid] = v;
    __syncthreads();
    if (wid == 0) {
        int wv = warp_sums[lane];
        #pragma unroll
        for (int off = 1; off < 32; off <<= 1) {
            int n = __shfl_up_sync(0xffffffff, wv, off);
            if (lane >= off) wv += n;
        }
        warp_sums[lane] = wv;
    }
    __syncthreads();
    int prefix = v - local;                        // exclusive within warp-segment
    if (wid > 0) prefix += warp_sums[wid - 1];     // add preceding warps

    int run = prefix;
    for (int i = begin; i < end; i++) {
        int c = g_hist_in[i];
        g_row_start[i] = run;
        g_cursor[i]    = run;
        run += c;
    }
    if (t == T - 1) g_row_start[N_NODES] = run;
}

// Scatter edges into CSR-by-dst order; coefficient computed inline (shared by
// both layers: node-side rsqrt degree scalings commute into the edge scalar).
__global__ void scatter_kernel(const int* __restrict__ src,
                               const int* __restrict__ dst,
                               const float* __restrict__ w) {
    int e = blockIdx.x * blockDim.x + threadIdx.x;
    if (e >= N_EDGES) return;
    int s = src[e], d = dst[e];
    float c = w[e]
            * rsqrtf(fmaxf(g_wdeg_out[s], EPSW))
            * rsqrtf(fmaxf(g_wdeg_in [d], EPSW))
            * rsqrtf(fmaxf((float)g_cnt_out[s], 1.0f))
            * rsqrtf(fmaxf((float)g_hist_in[d], 1.0f));
    int pos = atomicAdd(&g_cursor[d], 1);
    g_csr_src [pos] = s;
    g_csr_coef[pos] = c;
}

// One warp per destination node: gather+accumulate in registers, one store.
// layer selects the feature source INSIDE the kernel (device symbol addresses
// are not valid from host code).
__global__ void spmm_csr_kernel(const float* __restrict__ x, int layer) {
    int warp = (blockIdx.x * blockDim.x + threadIdx.x) >> 5;
    int lane = threadIdx.x & 31;
    if (warp >= N_NODES) return;

    const float* feat = (layer == 0) ? x : g_h;

    int beg = g_row_start[warp];
    int end = g_row_start[warp + 1];

    float4 acc = make_float4(0.f, 0.f, 0.f, 0.f);
    int i = beg;
    // 2-wide unroll: two independent gathers in flight
    for (; i + 1 < end; i += 2) {
        int   s0 = g_csr_src[i],     s1 = g_csr_src[i + 1];
        float c0 = g_csr_coef[i],    c1 = g_csr_coef[i + 1];
        float4 v0 = *((const float4*)(feat + (size_t)s0 * F) + lane);
        float4 v1 = *((const float4*)(feat + (size_t)s1 * F) + lane);
        acc.x = fmaf(c0, v0.x, acc.x);
        acc.y = fmaf(c0, v0.y, acc.y);
        acc.z = fmaf(c0, v0.z, acc.z);
        acc.w = fmaf(c0, v0.w, acc.w);
        acc.x = fmaf(c1, v1.x, acc.x);
        acc.y = fmaf(c1, v1.y, acc.y);
        acc.z = fmaf(c1, v1.z, acc.z);
        acc.w = fmaf(c1, v1.w, acc.w);
    }
    if (i < end) {
        int   s = g_csr_src[i];
        float c = g_csr_coef[i];
        float4 v = *((const float4*)(feat + (size_t)s * F) + lane);
        acc.x = fmaf(c, v.x, acc.x);
        acc.y = fmaf(c, v.y, acc.y);
        acc.z = fmaf(c, v.z, acc.z);
        acc.w = fmaf(c, v.w, acc.w);
    }
    *((float4*)(g_agg + (size_t)warp * F) + lane) = acc;
}

// C = selu(g_agg @ W + b).  M = N_NODES, N = K = 128.
// Block: 256 threads, 128x128 tile, 8x8 micro-tile per thread, BK = 8.
__global__ void gemm_bias_selu_kernel(const float* __restrict__ W,
                                      const float* __restrict__ b,
                                      float* __restrict__ outp,
                                      int layer) {
    __shared__ float As[8][128];   // transposed A tile: As[k][m]
    __shared__ float Bs[8][128];   // Bs[k][n]

    const float* A = g_agg;
    float* out = (layer == 0) ? g_h : outp;

    int tid = threadIdx.x;
    int bm = blockIdx.x * 128;
    int ty = tid >> 4;
    int tx = tid & 15;

    float acc[8][8];
#pragma unroll
    for (int i = 0; i < 8; i++)
#pragma unroll
        for (int j = 0; j < 8; j++) acc[i][j] = 0.0f;

    int am = tid >> 1;
    int akq = (tid & 1) * 4;
    int arow = bm + am;
    int bkb = tid >> 5;
    int bnb = (tid & 31) * 4;

    for (int k0 = 0; k0 < 128; k0 += 8) {
        float4 av = make_float4(0.f, 0.f, 0.f, 0.f);
        if (arow < N_NODES)
            av = *(const float4*)(A + (size_t)arow * F + k0 + akq);
        As[akq + 0][am] = av.x;
        As[akq + 1][am] = av.y;
        As[akq + 2][am] = av.z;
        As[akq + 3][am] = av.w;

        *(float4*)&Bs[bkb][bnb] = *(const float4*)(W + (size_t)(k0 + bkb) * F + bnb);

        __syncthreads();

#pragma unroll
        for (int k = 0; k < 8; k++) {
            float a[8], bb[8];
#pragma unroll
            for (int i = 0; i < 8; i++) a[i] = As[k][ty * 8 + i];
#pragma unroll
            for (int j = 0; j < 8; j++) bb[j] = Bs[k][tx * 8 + j];
#pragma unroll
            for (int i = 0; i < 8; i++)
#pragma unroll
                for (int j = 0; j < 8; j++)
                    acc[i][j] = fmaf(a[i], bb[j], acc[i][j]);
        }
        __syncthreads();
    }

#pragma unroll
    for (int i = 0; i < 8; i++) {
        int row = bm + ty * 8 + i;
        if (row >= N_NODES) continue;
#pragma unroll
        for (int j = 0; j < 8; j++) {
            int col = tx * 8 + j;
            float v = acc[i][j] + b[col];
            out[(size_t)row * F + col] = selu_f(v);
        }
    }
}

// ---------------- launch ----------------------------------------------------
extern "C" void kernel_launch(void* const* d_in, const int* in_sizes, int n_in,
                              void* d_out, int out_size) {
    const float* x   = (const float*)d_in[0];
    const int*   src = (const int*)  d_in[1];
    const int*   dst = (const int*)  d_in[2];
    const float* ew  = (const float*)d_in[3];
    const float* W1  = (const float*)d_in[4];
    const float* b1  = (const float*)d_in[5];
    const float* W2  = (const float*)d_in[6];
    const float* b2  = (const float*)d_in[7];
    float* out = (float*)d_out;

    const int TB = 256;
    dim3 nodeGrid((N_NODES + TB - 1) / TB);
    dim3 edgeGrid((N_EDGES + TB - 1) / TB);
    dim3 spmmGrid(((size_t)N_NODES * 32 + TB - 1) / TB);
    dim3 gemmGrid((N_NODES + 127) / 128);

    // CSR build (shared by both layers)
    zero_deg_kernel<<<nodeGrid, TB>>>();
    deg_kernel<<<edgeGrid, TB>>>(src, dst, ew);
    scan_kernel<<<1, 1024>>>();
    scatter_kernel<<<edgeGrid, TB>>>(src, dst, ew);

    // layer 1
    spmm_csr_kernel<<<spmmGrid, TB>>>(x, 0);
    gemm_bias_selu_kernel<<<gemmGrid, TB>>>(W1, b1, out, 0);

    // layer 2
    spmm_csr_kernel<<<spmmGrid, TB>>>(x, 1);
    gemm_bias_selu_kernel<<<gemmGrid, TB>>>(W2, b2, out, 1);
}

// round 5
// speedup vs baseline: 2.4619x; 1.3827x over previous
#include <cuda_runtime.h>
#include <cuda_bf16.h>
#include <math.h>
#include <stdint.h>

#define N_NODES 50000
#define N_EDGES 800000
#define F 128
#define EPSW 1e-12f
#define ASTRIDE 264   // bf16 elems per SMEM row: 256 data + 8 pad (conflict-free)

// ---------------- scratch (device globals; no allocation allowed) ----------
__device__ float g_wdeg_out[N_NODES];
__device__ float g_wdeg_in [N_NODES];
__device__ int   g_cnt_out [N_NODES];
__device__ int   g_hist_in [N_NODES];
__device__ int   g_row_start[N_NODES + 1];
__device__ int   g_cursor  [N_NODES];
__device__ int   g_csr_src [N_EDGES];
__device__ float g_csr_coef[N_EDGES];
__device__ float g_agg     [(size_t)N_NODES * F];
__device__ float g_h       [(size_t)N_NODES * F];
// B' = hi/lo-split transposed weights: [layer][n][k'] k'<128 = hi, k'>=128 = lo
__device__ __nv_bfloat16 g_bp[2 * 128 * 256];

// ---------------- helpers ---------------------------------------------------
__device__ __forceinline__ float selu_f(float v) {
    const float scale = 1.0507009873554805f;
    const float alpha = 1.6732632423543772f;
    return v > 0.0f ? scale * v : scale * alpha * expm1f(v);
}

__device__ __forceinline__ uint32_t pack_bf16x2(__nv_bfloat16 a, __nv_bfloat16 b) {
    return (uint32_t)__bfloat16_as_ushort(a) | ((uint32_t)__bfloat16_as_ushort(b) << 16);
}

__device__ __forceinline__ void mma16816(float c[4], const uint32_t a[4],
                                         const uint32_t b[2]) {
    asm volatile(
        "mma.sync.aligned.m16n8k16.row.col.f32.bf16.bf16.f32 "
        "{%0,%1,%2,%3}, {%4,%5,%6,%7}, {%8,%9}, {%0,%1,%2,%3};"
        : "+f"(c[0]), "+f"(c[1]), "+f"(c[2]), "+f"(c[3])
        : "r"(a[0]), "r"(a[1]), "r"(a[2]), "r"(a[3]), "r"(b[0]), "r"(b[1]));
}

// ---------------- CSR build kernels ------------------------------------------
__global__ void zero_deg_kernel() {
    int i = blockIdx.x * blockDim.x + threadIdx.x;
    if (i < N_NODES) {
        g_wdeg_out[i] = 0.0f;
        g_wdeg_in [i] = 0.0f;
        g_cnt_out [i] = 0;
        g_hist_in [i] = 0;
    }
}

__global__ void deg_kernel(const int* __restrict__ src,
                           const int* __restrict__ dst,
                           const float* __restrict__ w) {
    int e = blockIdx.x * blockDim.x + threadIdx.x;
    if (e >= N_EDGES) return;
    float we = w[e];
    int s = src[e], d = dst[e];
    atomicAdd(&g_wdeg_out[s], we);
    atomicAdd(&g_wdeg_in [d], we);
    atomicAdd(&g_cnt_out [s], 1);
    atomicAdd(&g_hist_in [d], 1);
}

__global__ void scan_kernel() {
    const int T = 1024;
    __shared__ int warp_sums[32];
    int t = threadIdx.x;
    const int chunk = (N_NODES + T - 1) / T;
    int begin = t * chunk;
    int end = min(begin + chunk, N_NODES);

    int local = 0;
    for (int i = begin; i < end; i++) local += g_hist_in[i];

    int lane = t & 31, wid = t >> 5;
    int v = local;
    #pragma unroll
    for (int off = 1; off < 32; off <<= 1) {
        int n = __shfl_up_sync(0xffffffff, v, off);
        if (lane >= off) v += n;
    }
    if (lane == 31) warp_sums[wid] = v;
    __syncthreads();
    if (wid == 0) {
        int wv = warp_sums[lane];
        #pragma unroll
        for (int off = 1; off < 32; off <<= 1) {
            int n = __shfl_up_sync(0xffffffff, wv, off);
            if (lane >= off) wv += n;
        }
        warp_sums[lane] = wv;
    }
    __syncthreads();
    int prefix = v - local;
    if (wid > 0) prefix += warp_sums[wid - 1];

    int run = prefix;
    for (int i = begin; i < end; i++) {
        int c = g_hist_in[i];
        g_row_start[i] = run;
        g_cursor[i]    = run;
        run += c;
    }
    if (t == T - 1) g_row_start[N_NODES] = run;
}

__global__ void scatter_kernel(const int* __restrict__ src,
                               const int* __restrict__ dst,
                               const float* __restrict__ w) {
    int e = blockIdx.x * blockDim.x + threadIdx.x;
    if (e >= N_EDGES) return;
    int s = src[e], d = dst[e];
    float c = w[e]
            * rsqrtf(fmaxf(g_wdeg_out[s], EPSW))
            * rsqrtf(fmaxf(g_wdeg_in [d], EPSW))
            * rsqrtf(fmaxf((float)g_cnt_out[s], 1.0f))
            * rsqrtf(fmaxf((float)g_hist_in[d], 1.0f));
    int pos = atomicAdd(&g_cursor[d], 1);
    g_csr_src [pos] = s;
    g_csr_coef[pos] = c;
}

// ---------------- SpMM (CSR by dst, warp per node) ---------------------------
__global__ void spmm_csr_kernel(const float* __restrict__ x, int layer) {
    int warp = (blockIdx.x * blockDim.x + threadIdx.x) >> 5;
    int lane = threadIdx.x & 31;
    if (warp >= N_NODES) return;

    const float* feat = (layer == 0) ? x : g_h;

    int beg = g_row_start[warp];
    int end = g_row_start[warp + 1];

    float4 acc = make_float4(0.f, 0.f, 0.f, 0.f);
    int i = beg;
    for (; i + 1 < end; i += 2) {
        int   s0 = g_csr_src[i],   s1 = g_csr_src[i + 1];
        float c0 = g_csr_coef[i],  c1 = g_csr_coef[i + 1];
        float4 v0 = *((const float4*)(feat + (size_t)s0 * F) + lane);
        float4 v1 = *((const float4*)(feat + (size_t)s1 * F) + lane);
        acc.x = fmaf(c0, v0.x, acc.x);
        acc.y = fmaf(c0, v0.y, acc.y);
        acc.z = fmaf(c0, v0.z, acc.z);
        acc.w = fmaf(c0, v0.w, acc.w);
        acc.x = fmaf(c1, v1.x, acc.x);
        acc.y = fmaf(c1, v1.y, acc.y);
        acc.z = fmaf(c1, v1.z, acc.z);
        acc.w = fmaf(c1, v1.w, acc.w);
    }
    if (i < end) {
        int   s = g_csr_src[i];
        float c = g_csr_coef[i];
        float4 v = *((const float4*)(feat + (size_t)s * F) + lane);
        acc.x = fmaf(c, v.x, acc.x);
        acc.y = fmaf(c, v.y, acc.y);
        acc.z = fmaf(c, v.z, acc.z);
        acc.w = fmaf(c, v.w, acc.w);
    }
    *((float4*)(g_agg + (size_t)warp * F) + lane) = acc;
}

// ---------------- weight prep: transpose + hi/lo bf16 split ------------------
__global__ void prep_w_kernel(const float* __restrict__ W1,
                              const float* __restrict__ W2) {
    int i = blockIdx.x * blockDim.x + threadIdx.x;
    if (i >= 128 * 128) return;
    int k = i >> 7, n = i & 127;
    #pragma unroll
    for (int layer = 0; layer < 2; layer++) {
        float v = (layer ? W2 : W1)[i];     // W[k][n]
        __nv_bfloat16 hi = __float2bfloat16(v);
        __nv_bfloat16 lo = __float2bfloat16(v - __bfloat162float(hi));
        g_bp[(size_t)layer * 32768 + n * 256 + k]       = hi;
        g_bp[(size_t)layer * 32768 + n * 256 + 128 + k] = lo;
    }
}

// ---------------- mma.sync bf16 GEMM: out = selu(agg @ W + b) ----------------
// 128x128 CTA tile, 8 warps (warp tile 32x64), hi/lo split = 3 passes of K=128.
__global__ void __launch_bounds__(256, 1)
gemm_mma_kernel(const float* __restrict__ bias, float* __restrict__ outp, int layer) {
    extern __shared__ __nv_bfloat16 smem[];
    __nv_bfloat16* sA = smem;                         // [128][ASTRIDE]
    __nv_bfloat16* sB = smem + 128 * ASTRIDE;         // [128][ASTRIDE]

    int tid = threadIdx.x;
    int wid = tid >> 5, lane = tid & 31;
    int g = lane >> 2, tg = lane & 3;
    int bm = blockIdx.x * 128;
    int warp_m = (wid & 3) * 32;
    int warp_n = (wid >> 2) * 64;

    // ---- load + split A tile (agg rows, fp32 -> bf16 hi|lo along k) ----
    #pragma unroll
    for (int it = 0; it < 16; it++) {
        int idx = it * 256 + tid;          // 0..4095 float4 units
        int r  = idx >> 5;                 // 0..127
        int kq = (idx & 31) * 4;           // 0..124
        float4 v = make_float4(0.f, 0.f, 0.f, 0.f);
        if (bm + r < N_NODES)
            v = *(const float4*)(g_agg + (size_t)(bm + r) * F + kq);

        __nv_bfloat16 h0 = __float2bfloat16(v.x);
        __nv_bfloat16 h1 = __float2bfloat16(v.y);
        __nv_bfloat16 h2 = __float2bfloat16(v.z);
        __nv_bfloat16 h3 = __float2bfloat16(v.w);
        __nv_bfloat16 l0 = __float2bfloat16(v.x - __bfloat162float(h0));
        __nv_bfloat16 l1 = __float2bfloat16(v.y - __bfloat162float(h1));
        __nv_bfloat16 l2 = __float2bfloat16(v.z - __bfloat162float(h2));
        __nv_bfloat16 l3 = __float2bfloat16(v.w - __bfloat162float(h3));

        uint2 hi2, lo2;
        hi2.x = pack_bf16x2(h0, h1); hi2.y = pack_bf16x2(h2, h3);
        lo2.x = pack_bf16x2(l0, l1); lo2.y = pack_bf16x2(l2, l3);
        *(uint2*)(sA + r * ASTRIDE + kq)       = hi2;
        *(uint2*)(sA + r * ASTRIDE + 128 + kq) = lo2;
    }

    // ---- load B' tile (pre-split [n][256] bf16) ----
    const __nv_bfloat16* bp = g_bp + (size_t)layer * 32768;
    #pragma unroll
    for (int it = 0; it < 16; it++) {
        int idx = it * 256 + tid;          // 0..4095 uint4 units
        int n  = idx >> 5;                 // 0..127
        int kp = (idx & 31) * 8;           // 0..248
        *(uint4*)(sB + n * ASTRIDE + kp) = *(const uint4*)(bp + (size_t)n * 256 + kp);
    }
    __syncthreads();

    // ---- mainloop: 3 passes (hi*hi, lo*hi, hi*lo) x 8 k-steps x 16 mma ----
    float c[2][8][4];
    #pragma unroll
    for (int mt = 0; mt < 2; mt++)
        #pragma unroll
        for (int nt = 0; nt < 8; nt++)
            #pragma unroll
            for (int q = 0; q < 4; q++) c[mt][nt][q] = 0.0f;

    #pragma unroll
    for (int pass = 0; pass < 3; pass++) {
        int aoff = (pass == 1) ? 128 : 0;
        int boff = (pass == 2) ? 128 : 0;
        #pragma unroll
        for (int k0 = 0; k0 < 128; k0 += 16) {
            uint32_t a[2][4], b[8][2];
            #pragma unroll
            for (int mt = 0; mt < 2; mt++) {
                const __nv_bfloat16* base =
                    sA + (warp_m + mt * 16 + g) * ASTRIDE + aoff + k0 + 2 * tg;
                a[mt][0] = *(const uint32_t*)(base);
                a[mt][1] = *(const uint32_t*)(base + 8 * ASTRIDE);
                a[mt][2] = *(const uint32_t*)(base + 8);
                a[mt][3] = *(const uint32_t*)(base + 8 * ASTRIDE + 8);
            }
            #pragma unroll
            for (int nt = 0; nt < 8; nt++) {
                const __nv_bfloat16* base =
                    sB + (warp_n + nt * 8 + g) * ASTRIDE + boff + k0 + 2 * tg;
                b[nt][0] = *(const uint32_t*)(base);
                b[nt][1] = *(const uint32_t*)(base + 8);
            }
            #pragma unroll
            for (int mt = 0; mt < 2; mt++)
                #pragma unroll
                for (int nt = 0; nt < 8; nt++)
                    mma16816(c[mt][nt], a[mt], b[nt]);
        }
    }

    // ---- epilogue: bias + selu, float2 stores ----
    float* outbuf = (layer == 0) ? g_h : outp;
    #pragma unroll
    for (int nt = 0; nt < 8; nt++) {
        int col = warp_n + nt * 8 + 2 * tg;
        float b0 = bias[col], b1 = bias[col + 1];
        #pragma unroll
        for (int mt = 0; mt < 2; mt++) {
            int row0 = bm + warp_m + mt * 16 + g;
            if (row0 < N_NODES) {
                float2 o;
                o.x = selu_f(c[mt][nt][0] + b0);
                o.y = selu_f(c[mt][nt][1] + b1);
                *(float2*)(outbuf + (size_t)row0 * F + col) = o;
            }
            int row1 = row0 + 8;
            if (row1 < N_NODES) {
                float2 o;
                o.x = selu_f(c[mt][nt][2] + b0);
                o.y = selu_f(c[mt][nt][3] + b1);
                *(float2*)(outbuf + (size_t)row1 * F + col) = o;
            }
        }
    }
}

// ---------------- launch ------------------------------------------------------
extern "C" void kernel_launch(void* const* d_in, const int* in_sizes, int n_in,
                              void* d_out, int out_size) {
    const float* x   = (const float*)d_in[0];
    const int*   src = (const int*)  d_in[1];
    const int*   dst = (const int*)  d_in[2];
    const float* ew  = (const float*)d_in[3];
    const float* W1  = (const float*)d_in[4];
    const float* b1  = (const float*)d_in[5];
    const float* W2  = (const float*)d_in[6];
    const float* b2  = (const float*)d_in[7];
    float* out = (float*)d_out;

    const int TB = 256;
    dim3 nodeGrid((N_NODES + TB - 1) / TB);
    dim3 edgeGrid((N_EDGES + TB - 1) / TB);
    dim3 spmmGrid(((size_t)N_NODES * 32 + TB - 1) / TB);
    dim3 gemmGrid((N_NODES + 127) / 128);
    const int GEMM_SMEM = 2 * 128 * ASTRIDE * 2;   // 135168 B

    cudaFuncSetAttribute(gemm_mma_kernel,
                         cudaFuncAttributeMaxDynamicSharedMemorySize, GEMM_SMEM);

    // weight prep + CSR build (shared by both layers)
    prep_w_kernel<<<64, 256>>>(W1, W2);
    zero_deg_kernel<<<nodeGrid, TB>>>();
    deg_kernel<<<edgeGrid, TB>>>(src, dst, ew);
    scan_kernel<<<1, 1024>>>();
    scatter_kernel<<<edgeGrid, TB>>>(src, dst, ew);

    // layer 1
    spmm_csr_kernel<<<spmmGrid, TB>>>(x, 0);
    gemm_mma_kernel<<<gemmGrid, 256, GEMM_SMEM>>>(b1, out, 0);

    // layer 2
    spmm_csr_kernel<<<spmmGrid, TB>>>(x, 1);
    gemm_mma_kernel<<<gemmGrid, 256, GEMM_SMEM>>>(b2, out, 1);
}

// round 6
// speedup vs baseline: 3.2961x; 1.3389x over previous
#include <cuda_runtime.h>
#include <cuda_bf16.h>
#include <math.h>
#include <stdint.h>

#define N_NODES 50000
#define N_EDGES 800000
#define F 128
#define EPSW 1e-12f
#define ASTRIDE 264   // bf16 elems per SMEM row: 256 data + 8 pad (conflict-free)

#define SCAN_BLOCKS 50
#define SCAN_CHUNK  1000   // SCAN_BLOCKS * SCAN_CHUNK == N_NODES

// ---------------- scratch (device globals; no allocation allowed) ----------
__device__ float g_wdeg_out[N_NODES];
__device__ float g_wdeg_in [N_NODES];
__device__ int   g_cnt_out [N_NODES];
__device__ int   g_hist_in [N_NODES];
__device__ int   g_row_start[N_NODES + 1];
__device__ int   g_cursor  [N_NODES];
__device__ int   g_blk_sum [SCAN_BLOCKS];
__device__ int   g_blk_off [SCAN_BLOCKS];
__device__ int   g_csr_src [N_EDGES];
__device__ float g_csr_coef[N_EDGES];
__device__ float g_agg     [(size_t)N_NODES * F];
__device__ float g_h       [(size_t)N_NODES * F];
// B' = hi/lo-split transposed weights: [layer][n][k'] k'<128 = hi, k'>=128 = lo
__device__ __nv_bfloat16 g_bp[2 * 128 * 256];

// ---------------- helpers ---------------------------------------------------
__device__ __forceinline__ float selu_f(float v) {
    const float scale = 1.0507009873554805f;
    const float alpha = 1.6732632423543772f;
    return v > 0.0f ? scale * v : scale * alpha * expm1f(v);
}

__device__ __forceinline__ uint32_t pack_bf16x2(__nv_bfloat16 a, __nv_bfloat16 b) {
    return (uint32_t)__bfloat16_as_ushort(a) | ((uint32_t)__bfloat16_as_ushort(b) << 16);
}

__device__ __forceinline__ void mma16816(float c[4], const uint32_t a[4],
                                         const uint32_t b[2]) {
    asm volatile(
        "mma.sync.aligned.m16n8k16.row.col.f32.bf16.bf16.f32 "
        "{%0,%1,%2,%3}, {%4,%5,%6,%7}, {%8,%9}, {%0,%1,%2,%3};"
        : "+f"(c[0]), "+f"(c[1]), "+f"(c[2]), "+f"(c[3])
        : "r"(a[0]), "r"(a[1]), "r"(a[2]), "r"(a[3]), "r"(b[0]), "r"(b[1]));
}

// ---------------- CSR build kernels ------------------------------------------
__global__ void zero_deg_kernel() {
    int i = blockIdx.x * blockDim.x + threadIdx.x;
    if (i < N_NODES) {
        g_wdeg_out[i] = 0.0f;
        g_wdeg_in [i] = 0.0f;
        g_cnt_out [i] = 0;
        g_hist_in [i] = 0;
    }
}

__global__ void deg_kernel(const int* __restrict__ src,
                           const int* __restrict__ dst,
                           const float* __restrict__ w) {
    int e = blockIdx.x * blockDim.x + threadIdx.x;
    if (e >= N_EDGES) return;
    float we = w[e];
    int s = src[e], d = dst[e];
    atomicAdd(&g_wdeg_out[s], we);
    atomicAdd(&g_wdeg_in [d], we);
    atomicAdd(&g_cnt_out [s], 1);
    atomicAdd(&g_hist_in [d], 1);
}

// ---- 3-stage scan: partial sums -> tiny scan -> in-block exclusive scan ----
__global__ void scan_part1() {
    __shared__ int wsum[8];
    int b = blockIdx.x, t = threadIdx.x;       // 256 threads
    int base = b * SCAN_CHUNK;
    int local = 0;
    #pragma unroll
    for (int j = 0; j < 4; j++) {
        int i = t * 4 + j;                     // threads 0..249 cover 1000
        if (i < SCAN_CHUNK) local += g_hist_in[base + i];
    }
    int lane = t & 31, wid = t >> 5;
    #pragma unroll
    for (int off = 16; off > 0; off >>= 1)
        local += __shfl_down_sync(0xffffffff, local, off);
    if (lane == 0) wsum[wid] = local;
    __syncthreads();
    if (t == 0) {
        int s = 0;
        #pragma unroll
        for (int k = 0; k < 8; k++) s += wsum[k];
        g_blk_sum[b] = s;
    }
}

__global__ void scan_part2() {
    __shared__ int sh[64];
    int t = threadIdx.x;                       // 64 threads
    sh[t] = (t < SCAN_BLOCKS) ? g_blk_sum[t] : 0;
    __syncthreads();
    // Hillis-Steele inclusive scan over 64 entries
    #pragma unroll
    for (int off = 1; off < 64; off <<= 1) {
        int v = (t >= off) ? sh[t - off] : 0;
        __syncthreads();
        sh[t] += v;
        __syncthreads();
    }
    if (t < SCAN_BLOCKS) g_blk_off[t] = sh[t] - g_blk_sum[t];   // exclusive
    if (t == SCAN_BLOCKS - 1) g_row_start[N_NODES] = sh[t];
}

__global__ void scan_part3() {
    __shared__ int wsum[8];
    int b = blockIdx.x, t = threadIdx.x;       // 256 threads
    int base = b * SCAN_CHUNK;
    int i0 = t * 4;
    int c0 = 0, c1 = 0, c2 = 0, c3 = 0;
    if (i0 < SCAN_CHUNK) {
        c0 = g_hist_in[base + i0];
        c1 = g_hist_in[base + i0 + 1];
        c2 = g_hist_in[base + i0 + 2];
        c3 = g_hist_in[base + i0 + 3];
    }
    int s = c0 + c1 + c2 + c3;

    int lane = t & 31, wid = t >> 5;
    int incl = s;
    #pragma unroll
    for (int off = 1; off < 32; off <<= 1) {
        int n = __shfl_up_sync(0xffffffff, incl, off);
        if (lane >= off) incl += n;
    }
    if (lane == 31) wsum[wid] = incl;
    __syncthreads();
    int wpre = 0;
    #pragma unroll
    for (int k = 0; k < 8; k++) wpre += (k < wid) ? wsum[k] : 0;

    if (i0 < SCAN_CHUNK) {
        int run = g_blk_off[b] + wpre + (incl - s);
        g_row_start[base + i0]     = run;  g_cursor[base + i0]     = run;  run += c0;
        g_row_start[base + i0 + 1] = run;  g_cursor[base + i0 + 1] = run;  run += c1;
        g_row_start[base + i0 + 2] = run;  g_cursor[base + i0 + 2] = run;  run += c2;
        g_row_start[base + i0 + 3] = run;  g_cursor[base + i0 + 3] = run;
    }
}

__global__ void scatter_kernel(const int* __restrict__ src,
                               const int* __restrict__ dst,
                               const float* __restrict__ w) {
    int e = blockIdx.x * blockDim.x + threadIdx.x;
    if (e >= N_EDGES) return;
    int s = src[e], d = dst[e];
    float c = w[e]
            * rsqrtf(fmaxf(g_wdeg_out[s], EPSW))
            * rsqrtf(fmaxf(g_wdeg_in [d], EPSW))
            * rsqrtf(fmaxf((float)g_cnt_out[s], 1.0f))
            * rsqrtf(fmaxf((float)g_hist_in[d], 1.0f));
    int pos = atomicAdd(&g_cursor[d], 1);
    g_csr_src [pos] = s;
    g_csr_coef[pos] = c;
}

// ---------------- SpMM (CSR by dst, warp per node) ---------------------------
__global__ void spmm_csr_kernel(const float* __restrict__ x, int layer) {
    int warp = (blockIdx.x * blockDim.x + threadIdx.x) >> 5;
    int lane = threadIdx.x & 31;
    if (warp >= N_NODES) return;

    const float* feat = (layer == 0) ? x : g_h;

    int beg = g_row_start[warp];
    int end = g_row_start[warp + 1];

    float4 acc = make_float4(0.f, 0.f, 0.f, 0.f);
    int i = beg;
    for (; i + 1 < end; i += 2) {
        int   s0 = g_csr_src[i],   s1 = g_csr_src[i + 1];
        float c0 = g_csr_coef[i],  c1 = g_csr_coef[i + 1];
        float4 v0 = *((const float4*)(feat + (size_t)s0 * F) + lane);
        float4 v1 = *((const float4*)(feat + (size_t)s1 * F) + lane);
        acc.x = fmaf(c0, v0.x, acc.x);
        acc.y = fmaf(c0, v0.y, acc.y);
        acc.z = fmaf(c0, v0.z, acc.z);
        acc.w = fmaf(c0, v0.w, acc.w);
        acc.x = fmaf(c1, v1.x, acc.x);
        acc.y = fmaf(c1, v1.y, acc.y);
        acc.z = fmaf(c1, v1.z, acc.z);
        acc.w = fmaf(c1, v1.w, acc.w);
    }
    if (i < end) {
        int   s = g_csr_src[i];
        float c = g_csr_coef[i];
        float4 v = *((const float4*)(feat + (size_t)s * F) + lane);
        acc.x = fmaf(c, v.x, acc.x);
        acc.y = fmaf(c, v.y, acc.y);
        acc.z = fmaf(c, v.z, acc.z);
        acc.w = fmaf(c, v.w, acc.w);
    }
    *((float4*)(g_agg + (size_t)warp * F) + lane) = acc;
}

// ---------------- weight prep: transpose + hi/lo bf16 split ------------------
__global__ void prep_w_kernel(const float* __restrict__ W1,
                              const float* __restrict__ W2) {
    int i = blockIdx.x * blockDim.x + threadIdx.x;
    if (i >= 128 * 128) return;
    int k = i >> 7, n = i & 127;
    #pragma unroll
    for (int layer = 0; layer < 2; layer++) {
        float v = (layer ? W2 : W1)[i];     // W[k][n]
        __nv_bfloat16 hi = __float2bfloat16(v);
        __nv_bfloat16 lo = __float2bfloat16(v - __bfloat162float(hi));
        g_bp[(size_t)layer * 32768 + n * 256 + k]       = hi;
        g_bp[(size_t)layer * 32768 + n * 256 + 128 + k] = lo;
    }
}

// ---------------- mma.sync bf16 GEMM: out = selu(agg @ W + b) ----------------
// 128x128 CTA tile, 8 warps (warp tile 32x64), hi/lo split = 3 passes of K=128.
__global__ void __launch_bounds__(256, 1)
gemm_mma_kernel(const float* __restrict__ bias, float* __restrict__ outp, int layer) {
    extern __shared__ __nv_bfloat16 smem[];
    __nv_bfloat16* sA = smem;                         // [128][ASTRIDE]
    __nv_bfloat16* sB = smem + 128 * ASTRIDE;         // [128][ASTRIDE]

    int tid = threadIdx.x;
    int wid = tid >> 5, lane = tid & 31;
    int g = lane >> 2, tg = lane & 3;
    int bm = blockIdx.x * 128;
    int warp_m = (wid & 3) * 32;
    int warp_n = (wid >> 2) * 64;

    // ---- load + split A tile (agg rows, fp32 -> bf16 hi|lo along k) ----
    #pragma unroll
    for (int it = 0; it < 16; it++) {
        int idx = it * 256 + tid;          // 0..4095 float4 units
        int r  = idx >> 5;                 // 0..127
        int kq = (idx & 31) * 4;           // 0..124
        float4 v = make_float4(0.f, 0.f, 0.f, 0.f);
        if (bm + r < N_NODES)
            v = *(const float4*)(g_agg + (size_t)(bm + r) * F + kq);

        __nv_bfloat16 h0 = __float2bfloat16(v.x);
        __nv_bfloat16 h1 = __float2bfloat16(v.y);
        __nv_bfloat16 h2 = __float2bfloat16(v.z);
        __nv_bfloat16 h3 = __float2bfloat16(v.w);
        __nv_bfloat16 l0 = __float2bfloat16(v.x - __bfloat162float(h0));
        __nv_bfloat16 l1 = __float2bfloat16(v.y - __bfloat162float(h1));
        __nv_bfloat16 l2 = __float2bfloat16(v.z - __bfloat162float(h2));
        __nv_bfloat16 l3 = __float2bfloat16(v.w - __bfloat162float(h3));

        uint2 hi2, lo2;
        hi2.x = pack_bf16x2(h0, h1); hi2.y = pack_bf16x2(h2, h3);
        lo2.x = pack_bf16x2(l0, l1); lo2.y = pack_bf16x2(l2, l3);
        *(uint2*)(sA + r * ASTRIDE + kq)       = hi2;
        *(uint2*)(sA + r * ASTRIDE + 128 + kq) = lo2;
    }

    // ---- load B' tile (pre-split [n][256] bf16) ----
    const __nv_bfloat16* bp = g_bp + (size_t)layer * 32768;
    #pragma unroll
    for (int it = 0; it < 16; it++) {
        int idx = it * 256 + tid;          // 0..4095 uint4 units
        int n  = idx >> 5;                 // 0..127
        int kp = (idx & 31) * 8;           // 0..248
        *(uint4*)(sB + n * ASTRIDE + kp) = *(const uint4*)(bp + (size_t)n * 256 + kp);
    }
    __syncthreads();

    // ---- mainloop: 3 passes (hi*hi, lo*hi, hi*lo) x 8 k-steps x 16 mma ----
    float c[2][8][4];
    #pragma unroll
    for (int mt = 0; mt < 2; mt++)
        #pragma unroll
        for (int nt = 0; nt < 8; nt++)
            #pragma unroll
            for (int q = 0; q < 4; q++) c[mt][nt][q] = 0.0f;

    #pragma unroll
    for (int pass = 0; pass < 3; pass++) {
        int aoff = (pass == 1) ? 128 : 0;
        int boff = (pass == 2) ? 128 : 0;
        #pragma unroll
        for (int k0 = 0; k0 < 128; k0 += 16) {
            uint32_t a[2][4], b[8][2];
            #pragma unroll
            for (int mt = 0; mt < 2; mt++) {
                const __nv_bfloat16* base =
                    sA + (warp_m + mt * 16 + g) * ASTRIDE + aoff + k0 + 2 * tg;
                a[mt][0] = *(const uint32_t*)(base);
                a[mt][1] = *(const uint32_t*)(base + 8 * ASTRIDE);
                a[mt][2] = *(const uint32_t*)(base + 8);
                a[mt][3] = *(const uint32_t*)(base + 8 * ASTRIDE + 8);
            }
            #pragma unroll
            for (int nt = 0; nt < 8; nt++) {
                const __nv_bfloat16* base =
                    sB + (warp_n + nt * 8 + g) * ASTRIDE + boff + k0 + 2 * tg;
                b[nt][0] = *(const uint32_t*)(base);
                b[nt][1] = *(const uint32_t*)(base + 8);
            }
            #pragma unroll
            for (int mt = 0; mt < 2; mt++)
                #pragma unroll
                for (int nt = 0; nt < 8; nt++)
                    mma16816(c[mt][nt], a[mt], b[nt]);
        }
    }

    // ---- epilogue: bias + selu, float2 stores ----
    float* outbuf = (layer == 0) ? g_h : outp;
    #pragma unroll
    for (int nt = 0; nt < 8; nt++) {
        int col = warp_n + nt * 8 + 2 * tg;
        float b0 = bias[col], b1 = bias[col + 1];
        #pragma unroll
        for (int mt = 0; mt < 2; mt++) {
            int row0 = bm + warp_m + mt * 16 + g;
            if (row0 < N_NODES) {
                float2 o;
                o.x = selu_f(c[mt][nt][0] + b0);
                o.y = selu_f(c[mt][nt][1] + b1);
                *(float2*)(outbuf + (size_t)row0 * F + col) = o;
            }
            int row1 = row0 + 8;
            if (row1 < N_NODES) {
                float2 o;
                o.x = selu_f(c[mt][nt][2] + b0);
                o.y = selu_f(c[mt][nt][3] + b1);
                *(float2*)(outbuf + (size_t)row1 * F + col) = o;
            }
        }
    }
}

// ---------------- launch ------------------------------------------------------
extern "C" void kernel_launch(void* const* d_in, const int* in_sizes, int n_in,
                              void* d_out, int out_size) {
    const float* x   = (const float*)d_in[0];
    const int*   src = (const int*)  d_in[1];
    const int*   dst = (const int*)  d_in[2];
    const float* ew  = (const float*)d_in[3];
    const float* W1  = (const float*)d_in[4];
    const float* b1  = (const float*)d_in[5];
    const float* W2  = (const float*)d_in[6];
    const float* b2  = (const float*)d_in[7];
    float* out = (float*)d_out;

    const int TB = 256;
    dim3 nodeGrid((N_NODES + TB - 1) / TB);
    dim3 edgeGrid((N_EDGES + TB - 1) / TB);
    dim3 spmmGrid(((size_t)N_NODES * 32 + TB - 1) / TB);
    dim3 gemmGrid((N_NODES + 127) / 128);
    const int GEMM_SMEM = 2 * 128 * ASTRIDE * 2;   // 135168 B

    cudaFuncSetAttribute(gemm_mma_kernel,
                         cudaFuncAttributeMaxDynamicSharedMemorySize, GEMM_SMEM);

    // weight prep + CSR build (shared by both layers)
    prep_w_kernel<<<64, 256>>>(W1, W2);
    zero_deg_kernel<<<nodeGrid, TB>>>();
    deg_kernel<<<edgeGrid, TB>>>(src, dst, ew);
    scan_part1<<<SCAN_BLOCKS, 256>>>();
    scan_part2<<<1, 64>>>();
    scan_part3<<<SCAN_BLOCKS, 256>>>();
    scatter_kernel<<<edgeGrid, TB>>>(src, dst, ew);

    // layer 1
    spmm_csr_kernel<<<spmmGrid, TB>>>(x, 0);
    gemm_mma_kernel<<<gemmGrid, 256, GEMM_SMEM>>>(b1, out, 0);

    // layer 2
    spmm_csr_kernel<<<spmmGrid, TB>>>(x, 1);
    gemm_mma_kernel<<<gemmGrid, 256, GEMM_SMEM>>>(b2, out, 1);
}

// round 7
// speedup vs baseline: 3.4333x; 1.0416x over previous
#include <cuda_runtime.h>
#include <cuda_bf16.h>
#include <math.h>
#include <stdint.h>

#define N_NODES 50000
#define N_EDGES 800000
#define F 128
#define EPSW 1e-12f
#define ASTRIDE 264   // bf16 elems per SMEM row: 256 data + 8 pad (conflict-free)

#define SCAN_BLOCKS 50
#define SCAN_CHUNK  1000   // SCAN_BLOCKS * SCAN_CHUNK == N_NODES

// ---------------- scratch (device globals; no allocation allowed) ----------
__device__ float g_wdeg_out[N_NODES];
__device__ float g_wdeg_in [N_NODES];
__device__ int   g_cnt_out [N_NODES];
__device__ int   g_hist_in [N_NODES];
__device__ int   g_row_start[N_NODES + 1];
__device__ int   g_cursor  [N_NODES];
__device__ int   g_blk_sum [SCAN_BLOCKS];
__device__ int   g_blk_off [SCAN_BLOCKS];
__device__ int2  g_csr     [N_EDGES];        // packed {src, coef bits}
__device__ float g_agg     [(size_t)N_NODES * F];
__device__ float g_h       [(size_t)N_NODES * F];
// B' = hi/lo-split transposed weights: [layer][n][k'] k'<128 = hi, k'>=128 = lo
__device__ __nv_bfloat16 g_bp[2 * 128 * 256];

// ---------------- helpers ---------------------------------------------------
__device__ __forceinline__ float selu_f(float v) {
    const float scale = 1.0507009873554805f;
    const float alpha = 1.6732632423543772f;
    return v > 0.0f ? scale * v : scale * alpha * expm1f(v);
}

__device__ __forceinline__ uint32_t pack_bf16x2(__nv_bfloat16 a, __nv_bfloat16 b) {
    return (uint32_t)__bfloat16_as_ushort(a) | ((uint32_t)__bfloat16_as_ushort(b) << 16);
}

__device__ __forceinline__ void mma16816(float c[4], const uint32_t a[4],
                                         const uint32_t b[2]) {
    asm volatile(
        "mma.sync.aligned.m16n8k16.row.col.f32.bf16.bf16.f32 "
        "{%0,%1,%2,%3}, {%4,%5,%6,%7}, {%8,%9}, {%0,%1,%2,%3};"
        : "+f"(c[0]), "+f"(c[1]), "+f"(c[2]), "+f"(c[3])
        : "r"(a[0]), "r"(a[1]), "r"(a[2]), "r"(a[3]), "r"(b[0]), "r"(b[1]));
}

// ---------------- CSR build kernels ------------------------------------------
__global__ void zero_deg_kernel() {
    int i = blockIdx.x * blockDim.x + threadIdx.x;
    if (i < N_NODES) {
        g_wdeg_out[i] = 0.0f;
        g_wdeg_in [i] = 0.0f;
        g_cnt_out [i] = 0;
        g_hist_in [i] = 0;
    }
}

__global__ void deg_kernel(const int* __restrict__ src,
                           const int* __restrict__ dst,
                           const float* __restrict__ w) {
    int e = blockIdx.x * blockDim.x + threadIdx.x;
    if (e >= N_EDGES) return;
    float we = w[e];
    int s = src[e], d = dst[e];
    atomicAdd(&g_wdeg_out[s], we);
    atomicAdd(&g_wdeg_in [d], we);
    atomicAdd(&g_cnt_out [s], 1);
    atomicAdd(&g_hist_in [d], 1);
}

// ---- 3-stage scan: partial sums -> tiny scan -> in-block exclusive scan ----
__global__ void scan_part1() {
    __shared__ int wsum[8];
    int b = blockIdx.x, t = threadIdx.x;       // 256 threads
    int base = b * SCAN_CHUNK;
    int local = 0;
    #pragma unroll
    for (int j = 0; j < 4; j++) {
        int i = t * 4 + j;                     // threads 0..249 cover 1000
        if (i < SCAN_CHUNK) local += g_hist_in[base + i];
    }
    int lane = t & 31, wid = t >> 5;
    #pragma unroll
    for (int off = 16; off > 0; off >>= 1)
        local += __shfl_down_sync(0xffffffff, local, off);
    if (lane == 0) wsum[wid] = local;
    __syncthreads();
    if (t == 0) {
        int s = 0;
        #pragma unroll
        for (int k = 0; k < 8; k++) s += wsum[k];
        g_blk_sum[b] = s;
    }
}

__global__ void scan_part2() {
    __shared__ int sh[64];
    int t = threadIdx.x;                       // 64 threads
    sh[t] = (t < SCAN_BLOCKS) ? g_blk_sum[t] : 0;
    __syncthreads();
    #pragma unroll
    for (int off = 1; off < 64; off <<= 1) {
        int v = (t >= off) ? sh[t - off] : 0;
        __syncthreads();
        sh[t] += v;
        __syncthreads();
    }
    if (t < SCAN_BLOCKS) g_blk_off[t] = sh[t] - g_blk_sum[t];   // exclusive
    if (t == SCAN_BLOCKS - 1) g_row_start[N_NODES] = sh[t];
}

__global__ void scan_part3() {
    __shared__ int wsum[8];
    int b = blockIdx.x, t = threadIdx.x;       // 256 threads
    int base = b * SCAN_CHUNK;
    int i0 = t * 4;
    int c0 = 0, c1 = 0, c2 = 0, c3 = 0;
    if (i0 < SCAN_CHUNK) {
        c0 = g_hist_in[base + i0];
        c1 = g_hist_in[base + i0 + 1];
        c2 = g_hist_in[base + i0 + 2];
        c3 = g_hist_in[base + i0 + 3];
    }
    int s = c0 + c1 + c2 + c3;

    int lane = t & 31, wid = t >> 5;
    int incl = s;
    #pragma unroll
    for (int off = 1; off < 32; off <<= 1) {
        int n = __shfl_up_sync(0xffffffff, incl, off);
        if (lane >= off) incl += n;
    }
    if (lane == 31) wsum[wid] = incl;
    __syncthreads();
    int wpre = 0;
    #pragma unroll
    for (int k = 0; k < 8; k++) wpre += (k < wid) ? wsum[k] : 0;

    if (i0 < SCAN_CHUNK) {
        int run = g_blk_off[b] + wpre + (incl - s);
        g_row_start[base + i0]     = run;  g_cursor[base + i0]     = run;  run += c0;
        g_row_start[base + i0 + 1] = run;  g_cursor[base + i0 + 1] = run;  run += c1;
        g_row_start[base + i0 + 2] = run;  g_cursor[base + i0 + 2] = run;  run += c2;
        g_row_start[base + i0 + 3] = run;  g_cursor[base + i0 + 3] = run;
    }
}

__global__ void scatter_kernel(const int* __restrict__ src,
                               const int* __restrict__ dst,
                               const float* __restrict__ w) {
    int e = blockIdx.x * blockDim.x + threadIdx.x;
    if (e >= N_EDGES) return;
    int s = src[e], d = dst[e];
    float c = w[e]
            * rsqrtf(fmaxf(g_wdeg_out[s], EPSW))
            * rsqrtf(fmaxf(g_wdeg_in [d], EPSW))
            * rsqrtf(fmaxf((float)g_cnt_out[s], 1.0f))
            * rsqrtf(fmaxf((float)g_hist_in[d], 1.0f));
    int pos = atomicAdd(&g_cursor[d], 1);
    g_csr[pos] = make_int2(s, __float_as_int(c));   // single 8B store
}

// ---------------- SpMM (CSR by dst, warp per node, 4-wide MLP) ---------------
__global__ void spmm_csr_kernel(const float* __restrict__ x, int layer) {
    int warp = (blockIdx.x * blockDim.x + threadIdx.x) >> 5;
    int lane = threadIdx.x & 31;
    if (warp >= N_NODES) return;

    const float* feat = (layer == 0) ? x : g_h;

    int beg = g_row_start[warp];
    int end = g_row_start[warp + 1];

    float4 acc = make_float4(0.f, 0.f, 0.f, 0.f);
    int i = beg;
    for (; i + 3 < end; i += 4) {
        int2 p0 = g_csr[i];
        int2 p1 = g_csr[i + 1];
        int2 p2 = g_csr[i + 2];
        int2 p3 = g_csr[i + 3];
        float4 v0 = *((const float4*)(feat + (size_t)p0.x * F) + lane);
        float4 v1 = *((const float4*)(feat + (size_t)p1.x * F) + lane);
        float4 v2 = *((const float4*)(feat + (size_t)p2.x * F) + lane);
        float4 v3 = *((const float4*)(feat + (size_t)p3.x * F) + lane);
        float c0 = __int_as_float(p0.y), c1 = __int_as_float(p1.y);
        float c2 = __int_as_float(p2.y), c3 = __int_as_float(p3.y);
        acc.x = fmaf(c0, v0.x, acc.x); acc.y = fmaf(c0, v0.y, acc.y);
        acc.z = fmaf(c0, v0.z, acc.z); acc.w = fmaf(c0, v0.w, acc.w);
        acc.x = fmaf(c1, v1.x, acc.x); acc.y = fmaf(c1, v1.y, acc.y);
        acc.z = fmaf(c1, v1.z, acc.z); acc.w = fmaf(c1, v1.w, acc.w);
        acc.x = fmaf(c2, v2.x, acc.x); acc.y = fmaf(c2, v2.y, acc.y);
        acc.z = fmaf(c2, v2.z, acc.z); acc.w = fmaf(c2, v2.w, acc.w);
        acc.x = fmaf(c3, v3.x, acc.x); acc.y = fmaf(c3, v3.y, acc.y);
        acc.z = fmaf(c3, v3.z, acc.z); acc.w = fmaf(c3, v3.w, acc.w);
    }
    for (; i < end; i++) {
        int2 p = g_csr[i];
        float c = __int_as_float(p.y);
        float4 v = *((const float4*)(feat + (size_t)p.x * F) + lane);
        acc.x = fmaf(c, v.x, acc.x); acc.y = fmaf(c, v.y, acc.y);
        acc.z = fmaf(c, v.z, acc.z); acc.w = fmaf(c, v.w, acc.w);
    }
    *((float4*)(g_agg + (size_t)warp * F) + lane) = acc;
}

// ---------------- weight prep: transpose + hi/lo bf16 split ------------------
__global__ void prep_w_kernel(const float* __restrict__ W1,
                              const float* __restrict__ W2) {
    int i = blockIdx.x * blockDim.x + threadIdx.x;
    if (i >= 128 * 128) return;
    int k = i >> 7, n = i & 127;
    #pragma unroll
    for (int layer = 0; layer < 2; layer++) {
        float v = (layer ? W2 : W1)[i];     // W[k][n]
        __nv_bfloat16 hi = __float2bfloat16(v);
        __nv_bfloat16 lo = __float2bfloat16(v - __bfloat162float(hi));
        g_bp[(size_t)layer * 32768 + n * 256 + k]       = hi;
        g_bp[(size_t)layer * 32768 + n * 256 + 128 + k] = lo;
    }
}

// ---------------- mma.sync bf16 GEMM: out = selu(agg @ W + b) ----------------
// 128x128 CTA tile, 8 warps (warp tile 32x64), hi/lo split = 3 passes of K=128.
__global__ void __launch_bounds__(256, 1)
gemm_mma_kernel(const float* __restrict__ bias, float* __restrict__ outp, int layer) {
    extern __shared__ __nv_bfloat16 smem[];
    __nv_bfloat16* sA = smem;                         // [128][ASTRIDE]
    __nv_bfloat16* sB = smem + 128 * ASTRIDE;         // [128][ASTRIDE]

    int tid = threadIdx.x;
    int wid = tid >> 5, lane = tid & 31;
    int g = lane >> 2, tg = lane & 3;
    int bm = blockIdx.x * 128;
    int warp_m = (wid & 3) * 32;
    int warp_n = (wid >> 2) * 64;

    // ---- load + split A tile (agg rows, fp32 -> bf16 hi|lo along k) ----
    #pragma unroll
    for (int it = 0; it < 16; it++) {
        int idx = it * 256 + tid;          // 0..4095 float4 units
        int r  = idx >> 5;                 // 0..127
        int kq = (idx & 31) * 4;           // 0..124
        float4 v = make_float4(0.f, 0.f, 0.f, 0.f);
        if (bm + r < N_NODES)
            v = *(const float4*)(g_agg + (size_t)(bm + r) * F + kq);

        __nv_bfloat16 h0 = __float2bfloat16(v.x);
        __nv_bfloat16 h1 = __float2bfloat16(v.y);
        __nv_bfloat16 h2 = __float2bfloat16(v.z);
        __nv_bfloat16 h3 = __float2bfloat16(v.w);
        __nv_bfloat16 l0 = __float2bfloat16(v.x - __bfloat162float(h0));
        __nv_bfloat16 l1 = __float2bfloat16(v.y - __bfloat162float(h1));
        __nv_bfloat16 l2 = __float2bfloat16(v.z - __bfloat162float(h2));
        __nv_bfloat16 l3 = __float2bfloat16(v.w - __bfloat162float(h3));

        uint2 hi2, lo2;
        hi2.x = pack_bf16x2(h0, h1); hi2.y = pack_bf16x2(h2, h3);
        lo2.x = pack_bf16x2(l0, l1); lo2.y = pack_bf16x2(l2, l3);
        *(uint2*)(sA + r * ASTRIDE + kq)       = hi2;
        *(uint2*)(sA + r * ASTRIDE + 128 + kq) = lo2;
    }

    // ---- load B' tile (pre-split [n][256] bf16) ----
    const __nv_bfloat16* bp = g_bp + (size_t)layer * 32768;
    #pragma unroll
    for (int it = 0; it < 16; it++) {
        int idx = it * 256 + tid;          // 0..4095 uint4 units
        int n  = idx >> 5;                 // 0..127
        int kp = (idx & 31) * 8;           // 0..248
        *(uint4*)(sB + n * ASTRIDE + kp) = *(const uint4*)(bp + (size_t)n * 256 + kp);
    }
    __syncthreads();

    // ---- mainloop: 3 passes (hi*hi, lo*hi, hi*lo) x 8 k-steps x 16 mma ----
    float c[2][8][4];
    #pragma unroll
    for (int mt = 0; mt < 2; mt++)
        #pragma unroll
        for (int nt = 0; nt < 8; nt++)
            #pragma unroll
            for (int q = 0; q < 4; q++) c[mt][nt][q] = 0.0f;

    #pragma unroll
    for (int pass = 0; pass < 3; pass++) {
        int aoff = (pass == 1) ? 128 : 0;
        int boff = (pass == 2) ? 128 : 0;
        #pragma unroll
        for (int k0 = 0; k0 < 128; k0 += 16) {
            uint32_t a[2][4], b[8][2];
            #pragma unroll
            for (int mt = 0; mt < 2; mt++) {
                const __nv_bfloat16* base =
                    sA + (warp_m + mt * 16 + g) * ASTRIDE + aoff + k0 + 2 * tg;
                a[mt][0] = *(const uint32_t*)(base);
                a[mt][1] = *(const uint32_t*)(base + 8 * ASTRIDE);
                a[mt][2] = *(const uint32_t*)(base + 8);
                a[mt][3] = *(const uint32_t*)(base + 8 * ASTRIDE + 8);
            }
            #pragma unroll
            for (int nt = 0; nt < 8; nt++) {
                const __nv_bfloat16* base =
                    sB + (warp_n + nt * 8 + g) * ASTRIDE + boff + k0 + 2 * tg;
                b[nt][0] = *(const uint32_t*)(base);
                b[nt][1] = *(const uint32_t*)(base + 8);
            }
            #pragma unroll
            for (int mt = 0; mt < 2; mt++)
                #pragma unroll
                for (int nt = 0; nt < 8; nt++)
                    mma16816(c[mt][nt], a[mt], b[nt]);
        }
    }

    // ---- epilogue: bias + selu, float2 stores ----
    float* outbuf = (layer == 0) ? g_h : outp;
    #pragma unroll
    for (int nt = 0; nt < 8; nt++) {
        int col = warp_n + nt * 8 + 2 * tg;
        float b0 = bias[col], b1 = bias[col + 1];
        #pragma unroll
        for (int mt = 0; mt < 2; mt++) {
            int row0 = bm + warp_m + mt * 16 + g;
            if (row0 < N_NODES) {
                float2 o;
                o.x = selu_f(c[mt][nt][0] + b0);
                o.y = selu_f(c[mt][nt][1] + b1);
                *(float2*)(outbuf + (size_t)row0 * F + col) = o;
            }
            int row1 = row0 + 8;
            if (row1 < N_NODES) {
                float2 o;
                o.x = selu_f(c[mt][nt][2] + b0);
                o.y = selu_f(c[mt][nt][3] + b1);
                *(float2*)(outbuf + (size_t)row1 * F + col) = o;
            }
        }
    }
}

// ---------------- launch ------------------------------------------------------
extern "C" void kernel_launch(void* const* d_in, const int* in_sizes, int n_in,
                              void* d_out, int out_size) {
    const float* x   = (const float*)d_in[0];
    const int*   src = (const int*)  d_in[1];
    const int*   dst = (const int*)  d_in[2];
    const float* ew  = (const float*)d_in[3];
    const float* W1  = (const float*)d_in[4];
    const float* b1  = (const float*)d_in[5];
    const float* W2  = (const float*)d_in[6];
    const float* b2  = (const float*)d_in[7];
    float* out = (float*)d_out;

    const int TB = 256;
    dim3 nodeGrid((N_NODES + TB - 1) / TB);
    dim3 edgeGrid((N_EDGES + TB - 1) / TB);
    dim3 spmmGrid(((size_t)N_NODES * 32 + TB - 1) / TB);
    dim3 gemmGrid((N_NODES + 127) / 128);
    const int GEMM_SMEM = 2 * 128 * ASTRIDE * 2;   // 135168 B

    cudaFuncSetAttribute(gemm_mma_kernel,
                         cudaFuncAttributeMaxDynamicSharedMemorySize, GEMM_SMEM);

    // weight prep + CSR build (shared by both layers)
    prep_w_kernel<<<64, 256>>>(W1, W2);
    zero_deg_kernel<<<nodeGrid, TB>>>();
    deg_kernel<<<edgeGrid, TB>>>(src, dst, ew);
    scan_part1<<<SCAN_BLOCKS, 256>>>();
    scan_part2<<<1, 64>>>();
    scan_part3<<<SCAN_BLOCKS, 256>>>();
    scatter_kernel<<<edgeGrid, TB>>>(src, dst, ew);

    // layer 1
    spmm_csr_kernel<<<spmmGrid, TB>>>(x, 0);
    gemm_mma_kernel<<<gemmGrid, 256, GEMM_SMEM>>>(b1, out, 0);

    // layer 2
    spmm_csr_kernel<<<spmmGrid, TB>>>(x, 1);
    gemm_mma_kernel<<<gemmGrid, 256, GEMM_SMEM>>>(b2, out, 1);
}